// round 4
// baseline (speedup 1.0000x reference)
#include <cuda_runtime.h>
#include <cuda_bf16.h>
#include <cstdint>

// Tree constants (static given the reference's input construction)
//   DIM=3, FBITS=8, K=4, TREE_DEPTH=10, N leaves = 4^10 = 1048576
//   POS[t] = (4^t - 1) / 3 : start offset of level t in the flags array
//   Level-9 flags start at 87381; there are 262144 of them.
//
// Key identity: with PERMUTE = full 30-bit reversal,
//   X_rev = sum_t rev3(j_t) << (3*t)
// where j_t is the bit position chosen at level t (t=0 is the root).
// Then c0 = X_rev & 1023, c1 = (X_rev>>10)&1023, c2 = (X_rev>>20)&1023,
// and out[p] = (c0,c1,c2) * scale + offset.

#define N9_NODES 262144   // 4^9
#define BLOCK    256

__global__ void __launch_bounds__(BLOCK)
nbit_decode_kernel(const int* __restrict__ flags,
                   const float* __restrict__ offset,
                   const float* __restrict__ scale,
                   float* __restrict__ out)
{
    // LUT: for each byte value, packed rev3(position) of its set bits,
    // 3 bits per rank (ranks 0..3 used; flags have exactly 4 set bits).
    __shared__ unsigned lut[256];
    {
        unsigned v = threadIdx.x;            // BLOCK == 256 -> one entry each
        unsigned packed = 0;
        int rank = 0;
        #pragma unroll
        for (int b = 0; b < 8; ++b) {
            if ((v >> b) & 1u) {
                unsigned rb = ((b & 1u) << 2) | (b & 2u) | ((b >> 2) & 1u); // rev3
                if (rank < 8) packed |= rb << (3 * rank);
                ++rank;
            }
        }
        lut[v] = packed;
    }
    __syncthreads();

    const unsigned n9 = blockIdx.x * BLOCK + threadIdx.x;   // level-9 node id

    // Level start offsets (compile-time)
    const int POS0 = 0, POS1 = 1, POS2 = 5, POS3 = 21, POS4 = 85,
              POS5 = 341, POS6 = 1365, POS7 = 5461, POS8 = 21845, POS9 = 87381;

    unsigned acc = 0;

    // Levels 0..8 prefix. For level t: node n_t = n9 >> 2*(9-t),
    // child rank r_t = (n9 >> 2*(8-t)) & 3. Levels 0..4 are block-uniform.
    #pragma unroll
    for (int t = 0; t < 9; ++t) {
        const int pos = (t == 0) ? POS0 : (t == 1) ? POS1 : (t == 2) ? POS2 :
                        (t == 3) ? POS3 : (t == 4) ? POS4 : (t == 5) ? POS5 :
                        (t == 6) ? POS6 : (t == 7) ? POS7 : POS8;
        unsigned nt = n9 >> (2 * (9 - t));
        unsigned rt = (n9 >> (2 * (8 - t))) & 3u;
        unsigned f  = ((unsigned)__ldg(&flags[pos + (int)nt])) & 255u;
        unsigned contrib = (lut[f] >> (3u * rt)) & 7u;
        acc |= contrib << (3 * t);
    }

    // Level 9: one flag yields all four children (ranks 0..3)
    unsigned f9 = ((unsigned)__ldg(&flags[POS9 + (int)n9])) & 255u;
    unsigned p9 = lut[f9];

    const float s0 = __ldg(&scale[0]),  s1 = __ldg(&scale[1]),  s2 = __ldg(&scale[2]);
    const float o0 = __ldg(&offset[0]), o1 = __ldg(&offset[1]), o2 = __ldg(&offset[2]);

    // c0, c1 are shared by all 4 leaves of this thread (bits 0..19 of X_rev)
    const float v0 = (float)(acc & 1023u)         * s0 + o0;
    const float v1 = (float)((acc >> 10) & 1023u) * s1 + o1;
    const unsigned base_c2 = (acc >> 20) & 127u;  // bits 20..26; level 9 adds 27..29

    float vc[4];
    #pragma unroll
    for (int c = 0; c < 4; ++c) {
        unsigned c2 = base_c2 | (((p9 >> (3 * c)) & 7u) << 7);
        vc[c] = (float)c2 * s2 + o2;
    }

    // 4 leaves * 3 floats = 12 consecutive floats; 48B is 16B-aligned.
    float4* o4 = reinterpret_cast<float4*>(out + (size_t)n9 * 12u);
    o4[0] = make_float4(v0,    v1,    vc[0], v0);
    o4[1] = make_float4(v1,    vc[1], v0,    v1);
    o4[2] = make_float4(vc[2], v0,    v1,    vc[3]);
}

extern "C" void kernel_launch(void* const* d_in, const int* in_sizes, int n_in,
                              void* d_out, int out_size)
{
    // metadata order: flags (int32, 349525), offset (f32, 3), scale (f32, 3)
    const int*   flags  = (const int*)  d_in[0];
    const float* offset = (const float*)d_in[1];
    const float* scale  = (const float*)d_in[2];
    // Defensive: if the first input isn't the big flags array, find it by size.
    if (n_in == 3 && in_sizes[0] == 3) {
        // flags is whichever input has the large size
        int fi = (in_sizes[1] > 3) ? 1 : 2;
        flags = (const int*)d_in[fi];
        int s1 = -1, s2 = -1;
        for (int i = 0; i < 3; ++i) {
            if (i == fi) continue;
            if (s1 < 0) s1 = i; else s2 = i;
        }
        offset = (const float*)d_in[s1];
        scale  = (const float*)d_in[s2];
    }

    float* out = (float*)d_out;
    nbit_decode_kernel<<<N9_NODES / BLOCK, BLOCK>>>(flags, offset, scale, out);
}

// round 6
// speedup vs baseline: 1.1315x; 1.1315x over previous
#include <cuda_runtime.h>
#include <cuda_bf16.h>
#include <cstdint>

// Tree: DIM=3, FBITS=8, K=4, DEPTH=10, leaves = 4^10.
// POS[t] = (4^t-1)/3. Level-9 starts at 87381 (NOT 16B aligned -> scalar loads).
//
// Identity (verified in R4, rel_err 3e-8): with full 30-bit reversal,
//   X_rev = sum_t rev3(j_t) << 3t,  c0 = X&1023, c1=(X>>10)&1023, c2=X>>20.
//
// This version: one thread per LEVEL-8 node (16 leaves, 48 output floats).
// - levels 0..3: block-uniform -> computed once by thread 0, shared broadcast
// - levels 4..7: 4 coalesced LDG + shared-LUT lookups per thread
// - level 8:     1 LDG, pack gives all 4 child contributions
// - level 9:     4 consecutive LDG (children flags), packs give all 16 leaves
// c0,c1 constant per thread; c2 varies only in bits 4..9 across the 16 leaves.

#define BLOCK   128
#define NBLOCKS 512      // 65536 level-8 nodes

__global__ void __launch_bounds__(BLOCK)
nbit_decode_kernel(const int* __restrict__ flags,
                   const float* __restrict__ offset,
                   const float* __restrict__ scale,
                   float* __restrict__ out)
{
    // LUT: byte -> packed rev3(bit position) of its set bits, 3 bits per rank.
    __shared__ unsigned lut[256];
    __shared__ unsigned s_pre;

    const int tid = threadIdx.x;
    #pragma unroll
    for (int k = 0; k < 256 / BLOCK; ++k) {
        unsigned v = (unsigned)tid + k * BLOCK;
        unsigned packed = 0;
        int rank = 0;
        #pragma unroll
        for (int b = 0; b < 8; ++b) {
            if ((v >> b) & 1u) {
                unsigned rb = ((b & 1u) << 2) | (b & 2u) | ((b >> 2) & 1u); // rev3
                if (rank < 8) packed |= rb << (3 * rank);
                ++rank;
            }
        }
        lut[v] = packed;
    }
    __syncthreads();

    const unsigned n8base = blockIdx.x * BLOCK;

    // Block-uniform prefix: levels 0..3 (node AND rank uniform for 128
    // contiguous level-8 nodes: rank bits for t=3 are n8 bits 8..9).
    if (tid == 0) {
        const int P[4] = {0, 1, 5, 21};
        unsigned acc = 0;
        #pragma unroll
        for (int t = 0; t < 4; ++t) {
            unsigned nt = n8base >> (2 * (8 - t));
            unsigned rt = (n8base >> (2 * (7 - t))) & 3u;
            unsigned f  = ((unsigned)flags[P[t] + (int)nt]) & 255u;
            acc |= ((lut[f] >> (3 * rt)) & 7u) << (3 * t);
        }
        s_pre = acc;
    }
    __syncthreads();

    const unsigned n8 = n8base + tid;
    unsigned acc = s_pre;

    // Levels 4..7 (per-thread, heavily L1-broadcast for t=4..6)
    {
        const int P4 = 85, P5 = 341, P6 = 1365, P7 = 5461;
        unsigned f4 = ((unsigned)__ldg(&flags[P4 + (int)(n8 >> 8)])) & 255u;
        unsigned f5 = ((unsigned)__ldg(&flags[P5 + (int)(n8 >> 6)])) & 255u;
        unsigned f6 = ((unsigned)__ldg(&flags[P6 + (int)(n8 >> 4)])) & 255u;
        unsigned f7 = ((unsigned)__ldg(&flags[P7 + (int)(n8 >> 2)])) & 255u;
        acc |= ((lut[f4] >> (3u * ((n8 >> 6) & 3u))) & 7u) << 12;
        acc |= ((lut[f5] >> (3u * ((n8 >> 4) & 3u))) & 7u) << 15;
        acc |= ((lut[f6] >> (3u * ((n8 >> 2) & 3u))) & 7u) << 18;
        acc |= ((lut[f7] >> (3u * ( n8       & 3u))) & 7u) << 21;
    }

    // Level 8: one flag, pack covers ranks 0..3 (this thread's 4 children)
    unsigned p8 = lut[((unsigned)__ldg(&flags[21845 + (int)n8])) & 255u];

    // Level 9: children flags are 4 consecutive ints at 87381 + 4*n8
    unsigned f9[4];
    #pragma unroll
    for (int c = 0; c < 4; ++c)
        f9[c] = ((unsigned)__ldg(&flags[87381 + 4 * (int)n8 + c])) & 255u;

    const float s0 = __ldg(&scale[0]),  s1 = __ldg(&scale[1]),  s2 = __ldg(&scale[2]);
    const float o0 = __ldg(&offset[0]), o1 = __ldg(&offset[1]), o2 = __ldg(&offset[2]);

    // c0, c1 constant across all 16 leaves of this thread
    const float v0 = (float)(acc & 1023u)         * s0 + o0;
    const float v1 = (float)((acc >> 10) & 1023u) * s1 + o1;
    const unsigned base = (acc >> 20) & 15u;      // c2 bits 0..3

    float4* o4 = reinterpret_cast<float4*>(out + (size_t)n8 * 48u);

    #pragma unroll
    for (int r8 = 0; r8 < 4; ++r8) {
        unsigned mid = base | (((p8 >> (3 * r8)) & 7u) << 4);   // + c2 bits 4..6
        unsigned p9  = lut[f9[r8]];
        float vc0 = (float)(mid | (((p9      ) & 7u) << 7)) * s2 + o2;
        float vc1 = (float)(mid | (((p9 >> 3 ) & 7u) << 7)) * s2 + o2;
        float vc2 = (float)(mid | (((p9 >> 6 ) & 7u) << 7)) * s2 + o2;
        float vc3 = (float)(mid | (((p9 >> 9 ) & 7u) << 7)) * s2 + o2;
        o4[3 * r8 + 0] = make_float4(v0,  v1,  vc0, v0);
        o4[3 * r8 + 1] = make_float4(v1,  vc1, v0,  v1);
        o4[3 * r8 + 2] = make_float4(vc2, v0,  v1,  vc3);
    }
}

extern "C" void kernel_launch(void* const* d_in, const int* in_sizes, int n_in,
                              void* d_out, int out_size)
{
    const int*   flags  = (const int*)  d_in[0];
    const float* offset = (const float*)d_in[1];
    const float* scale  = (const float*)d_in[2];
    if (n_in == 3 && in_sizes[0] == 3) {   // defensive input-order handling
        int fi = (in_sizes[1] > 3) ? 1 : 2;
        flags = (const int*)d_in[fi];
        int s1 = -1, s2 = -1;
        for (int i = 0; i < 3; ++i) {
            if (i == fi) continue;
            if (s1 < 0) s1 = i; else s2 = i;
        }
        offset = (const float*)d_in[s1];
        scale  = (const float*)d_in[s2];
    }

    nbit_decode_kernel<<<NBLOCKS, BLOCK>>>(flags, offset, scale, (float*)d_out);
}